// round 2
// baseline (speedup 1.0000x reference)
#include <cuda_runtime.h>

// FlashAttention fp32 baseline for sm_103a.
// N=8192, D=128, no softmax scaling. Exact fp32 arithmetic (rel_err ~1e-6).
//
// CTA: 128 threads, BM=64 query rows, BN=64 keys per iteration.
// Thread grid 8(ty) x 16(tx):
//   QK phase: thread computes S[8 rows][4 strided cols], rows = ty*8+r,
//             cols = tx + 16*c  (strided cols -> conflict-light K reads)
//   PV phase: thread computes O[8 rows][8 contiguous d-cols], cols = tx*8..+7
// Smem: Q,K padded stride 132 floats (column reads across rows <=2-way),
//       V stride 128 (row-contiguous float4 reads), P stride 68.

#define N_SEQ 8192
#define DIM 128
#define BM 64
#define BN 64
#define QK_STRIDE 132
#define P_STRIDE 68

#define SMEM_FLOATS (BM * QK_STRIDE + BN * QK_STRIDE + BN * DIM + BM * P_STRIDE)

__global__ __launch_bounds__(128, 1)
void fa_fp32_kernel(const float* __restrict__ q,
                    const float* __restrict__ k,
                    const float* __restrict__ v,
                    float* __restrict__ out) {
    extern __shared__ float sm[];
    float* SQ = sm;                               // 64 x 132
    float* SK = SQ + BM * QK_STRIDE;              // 64 x 132
    float* SV = SK + BN * QK_STRIDE;              // 64 x 128
    float* SP = SV + BN * DIM;                    // 64 x 68

    const int tid = threadIdx.x;
    const int ty = tid >> 4;        // 0..7  -> owns rows ty*8 .. ty*8+7
    const int tx = tid & 15;        // 0..15
    const int qrow0 = blockIdx.x * BM;

    // ---- load Q tile (once) ----
    {
        const float4* qg = (const float4*)(q + (size_t)qrow0 * DIM);
        #pragma unroll
        for (int t = 0; t < 16; t++) {
            int i = tid + 128 * t;            // 2048 float4 total
            int row = i >> 5;                 // 32 float4 per row
            int dd = (i & 31) << 2;
            *(float4*)(SQ + row * QK_STRIDE + dd) = qg[i];
        }
    }

    float o[8][8];
    float m[8], l[8];
    #pragma unroll
    for (int r = 0; r < 8; r++) {
        m[r] = -1e30f;
        l[r] = 0.0f;
        #pragma unroll
        for (int c = 0; c < 8; c++) o[r][c] = 0.0f;
    }

    for (int kb = 0; kb < N_SEQ / BN; kb++) {
        __syncthreads();   // previous iter's smem reads done (also covers Q store, iter 0)

        // ---- stream K,V tiles into smem ----
        {
            const float4* kg = (const float4*)(k + (size_t)kb * BN * DIM);
            const float4* vg = (const float4*)(v + (size_t)kb * BN * DIM);
            #pragma unroll
            for (int t = 0; t < 16; t++) {
                int i = tid + 128 * t;
                int row = i >> 5;
                int dd = (i & 31) << 2;
                *(float4*)(SK + row * QK_STRIDE + dd) = kg[i];
                *(float4*)(SV + row * DIM + dd) = vg[i];
            }
        }
        __syncthreads();

        // ---- S = Q K^T ----
        float s[8][4];
        #pragma unroll
        for (int r = 0; r < 8; r++)
            #pragma unroll
            for (int c = 0; c < 4; c++) s[r][c] = 0.0f;

        #pragma unroll 4
        for (int dd = 0; dd < DIM; dd++) {
            float qs[8], ks[4];
            #pragma unroll
            for (int r = 0; r < 8; r++) qs[r] = SQ[(ty * 8 + r) * QK_STRIDE + dd];
            #pragma unroll
            for (int c = 0; c < 4; c++) ks[c] = SK[(tx + 16 * c) * QK_STRIDE + dd];
            #pragma unroll
            for (int r = 0; r < 8; r++)
                #pragma unroll
                for (int c = 0; c < 4; c++)
                    s[r][c] = fmaf(qs[r], ks[c], s[r][c]);
        }

        // ---- online softmax (rows owned by 16-lane tx-groups) ----
        #pragma unroll
        for (int r = 0; r < 8; r++) {
            float mx = fmaxf(fmaxf(s[r][0], s[r][1]), fmaxf(s[r][2], s[r][3]));
            #pragma unroll
            for (int w = 1; w < 16; w <<= 1)
                mx = fmaxf(mx, __shfl_xor_sync(0xffffffffu, mx, w));
            float mn = fmaxf(m[r], mx);
            float alpha = __expf(m[r] - mn);
            float rs = 0.0f;
            #pragma unroll
            for (int c = 0; c < 4; c++) {
                float p = __expf(s[r][c] - mn);
                s[r][c] = p;
                rs += p;
            }
            #pragma unroll
            for (int w = 1; w < 16; w <<= 1)
                rs += __shfl_xor_sync(0xffffffffu, rs, w);
            l[r] = l[r] * alpha + rs;
            m[r] = mn;
            #pragma unroll
            for (int c = 0; c < 8; c++) o[r][c] *= alpha;
            #pragma unroll
            for (int c = 0; c < 4; c++)
                SP[(ty * 8 + r) * P_STRIDE + tx + 16 * c] = s[r][c];
        }
        __syncthreads();

        // ---- O += P V ----
        #pragma unroll 2
        for (int j = 0; j < BN; j++) {
            float p8[8];
            #pragma unroll
            for (int r = 0; r < 8; r++) p8[r] = SP[(ty * 8 + r) * P_STRIDE + j];
            float4 v0 = *(const float4*)(SV + j * DIM + tx * 8);
            float4 v1 = *(const float4*)(SV + j * DIM + tx * 8 + 4);
            #pragma unroll
            for (int r = 0; r < 8; r++) {
                o[r][0] = fmaf(p8[r], v0.x, o[r][0]);
                o[r][1] = fmaf(p8[r], v0.y, o[r][1]);
                o[r][2] = fmaf(p8[r], v0.z, o[r][2]);
                o[r][3] = fmaf(p8[r], v0.w, o[r][3]);
                o[r][4] = fmaf(p8[r], v1.x, o[r][4]);
                o[r][5] = fmaf(p8[r], v1.y, o[r][5]);
                o[r][6] = fmaf(p8[r], v1.z, o[r][6]);
                o[r][7] = fmaf(p8[r], v1.w, o[r][7]);
            }
        }
    }

    // ---- normalize + store ----
    #pragma unroll
    for (int r = 0; r < 8; r++) {
        float inv = 1.0f / l[r];
        float4 a, b;
        a.x = o[r][0] * inv; a.y = o[r][1] * inv;
        a.z = o[r][2] * inv; a.w = o[r][3] * inv;
        b.x = o[r][4] * inv; b.y = o[r][5] * inv;
        b.z = o[r][6] * inv; b.w = o[r][7] * inv;
        float* op = out + (size_t)(qrow0 + ty * 8 + r) * DIM + tx * 8;
        *(float4*)(op) = a;
        *(float4*)(op + 4) = b;
    }
}

extern "C" void kernel_launch(void* const* d_in, const int* in_sizes, int n_in,
                              void* d_out, int out_size) {
    const float* q = (const float*)d_in[0];
    const float* k = (const float*)d_in[1];
    const float* v = (const float*)d_in[2];
    float* out = (float*)d_out;

    const int smem_bytes = SMEM_FLOATS * (int)sizeof(float);   // 117,760 B
    cudaFuncSetAttribute(fa_fp32_kernel,
                         cudaFuncAttributeMaxDynamicSharedMemorySize, smem_bytes);

    dim3 grid(N_SEQ / BM);   // 128 CTAs
    dim3 block(128);
    fa_fp32_kernel<<<grid, block, smem_bytes>>>(q, k, v, out);
}

// round 3
// speedup vs baseline: 2.1663x; 2.1663x over previous
#include <cuda_runtime.h>
#include <cstdint>

// FlashAttention via 3xTF32 mma.sync (emulated fp32 precision), sm_103a.
// N=8192, D=128, no softmax scaling.
// CTA: 128 threads (4 warps), BM=64 query rows (16/warp), BN=64 keys/iter.
// S = Ah*Bh + Ah*Bl + Al*Bh  (error ~eps^2, << 1e-3), same for P*V.

#define NSEQ 8192
#define DIM 128
#define BM 64
#define BN 64
#define SQK 132   // Q,K smem stride (floats): banks (4g+tig) conflict-free
#define SVS 136   // V smem stride: banks (8tig+g) conflict-free
#define SPS 132   // P smem stride

#define SMEM_FLOATS (BM * SQK + BN * SQK + BN * SVS + BM * SPS)

__device__ __forceinline__ uint32_t f2tf(float x) {
    uint32_t r;
    asm("cvt.rna.tf32.f32 %0, %1;" : "=r"(r) : "f"(x));
    return r;
}

// split x into tf32 hi + tf32 lo (x ~= hi + lo, residual ~eps^2*x)
__device__ __forceinline__ void tf_split(float x, uint32_t& hi, uint32_t& lo) {
    hi = f2tf(x);
    float l = x - __uint_as_float(hi);
    lo = f2tf(l);
}

__device__ __forceinline__ void mma_tf32(float* c, const uint32_t* a,
                                         uint32_t b0, uint32_t b1) {
    asm volatile(
        "mma.sync.aligned.m16n8k8.row.col.f32.tf32.tf32.f32 "
        "{%0,%1,%2,%3}, {%4,%5,%6,%7}, {%8,%9}, {%0,%1,%2,%3};"
        : "+f"(c[0]), "+f"(c[1]), "+f"(c[2]), "+f"(c[3])
        : "r"(a[0]), "r"(a[1]), "r"(a[2]), "r"(a[3]), "r"(b0), "r"(b1));
}

__global__ __launch_bounds__(128, 1)
void fa_tf32_kernel(const float* __restrict__ q,
                    const float* __restrict__ k,
                    const float* __restrict__ v,
                    float* __restrict__ out) {
    extern __shared__ float sm[];
    float* SQ = sm;                       // 64 x 132
    float* SK = SQ + BM * SQK;            // 64 x 132
    float* SV = SK + BN * SQK;            // 64 x 136
    float* SP = SV + BN * SVS;            // 64 x 132

    const int tid  = threadIdx.x;
    const int warp = tid >> 5;
    const int lane = tid & 31;
    const int g    = lane >> 2;   // group id (row within 8)
    const int tig  = lane & 3;    // thread in group
    const int wr   = warp * 16;   // this warp's row base in the 64-row tile
    const int qrow0 = blockIdx.x * BM;

    // ---- load Q tile once (fp32, stride 132) ----
    {
        const float4* qg = (const float4*)(q + (size_t)qrow0 * DIM);
        #pragma unroll
        for (int t = 0; t < 16; t++) {
            int i = tid + 128 * t;          // 2048 float4
            int row = i >> 5;
            int dd = (i & 31) << 2;
            *(float4*)(SQ + row * SQK + dd) = qg[i];
        }
    }

    // O accumulators: 16 n-tiles (D=128), c-frag layout
    float o[16][4];
    #pragma unroll
    for (int nt = 0; nt < 16; nt++)
        #pragma unroll
        for (int i = 0; i < 4; i++) o[nt][i] = 0.0f;

    float m0 = -1e30f, m1 = -1e30f, l0 = 0.0f, l1 = 0.0f;

    const float* Sq0 = SQ + (wr + g) * SQK;          // row g
    const float* Sq1 = Sq0 + 8 * SQK;                // row g+8
    float* Sp0w = SP + (wr + g) * SPS;
    float* Sp1w = Sp0w + 8 * SPS;

    #pragma unroll 1
    for (int kb = 0; kb < NSEQ / BN; kb++) {
        __syncthreads();  // previous iteration's SK/SV reads complete

        // ---- stream K,V tiles ----
        {
            const float4* kg = (const float4*)(k + (size_t)kb * BN * DIM);
            const float4* vg = (const float4*)(v + (size_t)kb * BN * DIM);
            #pragma unroll
            for (int t = 0; t < 16; t++) {
                int i = tid + 128 * t;
                int row = i >> 5;
                int dd = (i & 31) << 2;
                *(float4*)(SK + row * SQK + dd) = kg[i];
                *(float4*)(SV + row * SVS + dd) = vg[i];
            }
        }
        __syncthreads();

        // ---- S = Q K^T  (3x tf32 mma per tile) ----
        float s[8][4];
        #pragma unroll
        for (int nt = 0; nt < 8; nt++)
            #pragma unroll
            for (int i = 0; i < 4; i++) s[nt][i] = 0.0f;

        #pragma unroll 4
        for (int kc = 0; kc < DIM / 8; kc++) {
            uint32_t ah[4], al[4];
            tf_split(Sq0[8 * kc + tig],     ah[0], al[0]);
            tf_split(Sq1[8 * kc + tig],     ah[1], al[1]);
            tf_split(Sq0[8 * kc + tig + 4], ah[2], al[2]);
            tf_split(Sq1[8 * kc + tig + 4], ah[3], al[3]);

            #pragma unroll
            for (int nt = 0; nt < 8; nt++) {
                const float* kp = SK + (nt * 8 + g) * SQK + 8 * kc + tig;
                uint32_t bh0, bl0, bh1, bl1;
                tf_split(kp[0], bh0, bl0);
                tf_split(kp[4], bh1, bl1);
                mma_tf32(s[nt], ah, bh0, bh1);
                mma_tf32(s[nt], ah, bl0, bl1);
                mma_tf32(s[nt], al, bh0, bh1);
            }
        }

        // ---- online softmax (rows g and g+8; stats shared across quad) ----
        float mx0 = -1e30f, mx1 = -1e30f;
        #pragma unroll
        for (int nt = 0; nt < 8; nt++) {
            mx0 = fmaxf(mx0, fmaxf(s[nt][0], s[nt][1]));
            mx1 = fmaxf(mx1, fmaxf(s[nt][2], s[nt][3]));
        }
        mx0 = fmaxf(mx0, __shfl_xor_sync(0xffffffffu, mx0, 1));
        mx0 = fmaxf(mx0, __shfl_xor_sync(0xffffffffu, mx0, 2));
        mx1 = fmaxf(mx1, __shfl_xor_sync(0xffffffffu, mx1, 1));
        mx1 = fmaxf(mx1, __shfl_xor_sync(0xffffffffu, mx1, 2));

        float mn0 = fmaxf(m0, mx0);
        float mn1 = fmaxf(m1, mx1);
        float alpha0 = __expf(m0 - mn0);
        float alpha1 = __expf(m1 - mn1);
        m0 = mn0; m1 = mn1;

        float sum0 = 0.0f, sum1 = 0.0f;
        #pragma unroll
        for (int nt = 0; nt < 8; nt++) {
            s[nt][0] = __expf(s[nt][0] - mn0);
            s[nt][1] = __expf(s[nt][1] - mn0);
            s[nt][2] = __expf(s[nt][2] - mn1);
            s[nt][3] = __expf(s[nt][3] - mn1);
            sum0 += s[nt][0] + s[nt][1];
            sum1 += s[nt][2] + s[nt][3];
        }
        sum0 += __shfl_xor_sync(0xffffffffu, sum0, 1);
        sum0 += __shfl_xor_sync(0xffffffffu, sum0, 2);
        sum1 += __shfl_xor_sync(0xffffffffu, sum1, 1);
        sum1 += __shfl_xor_sync(0xffffffffu, sum1, 2);
        l0 = l0 * alpha0 + sum0;
        l1 = l1 * alpha1 + sum1;

        #pragma unroll
        for (int nt = 0; nt < 16; nt++) {
            o[nt][0] *= alpha0; o[nt][1] *= alpha0;
            o[nt][2] *= alpha1; o[nt][3] *= alpha1;
        }

        // ---- P to per-warp smem (read back as A-fragments) ----
        #pragma unroll
        for (int nt = 0; nt < 8; nt++) {
            *(float2*)(Sp0w + 8 * nt + 2 * tig) = make_float2(s[nt][0], s[nt][1]);
            *(float2*)(Sp1w + 8 * nt + 2 * tig) = make_float2(s[nt][2], s[nt][3]);
        }
        __syncwarp();

        // ---- O += P V  (3x tf32 mma per tile) ----
        #pragma unroll 2
        for (int kc = 0; kc < BN / 8; kc++) {
            uint32_t ah[4], al[4];
            tf_split(Sp0w[8 * kc + tig],     ah[0], al[0]);
            tf_split(Sp1w[8 * kc + tig],     ah[1], al[1]);
            tf_split(Sp0w[8 * kc + tig + 4], ah[2], al[2]);
            tf_split(Sp1w[8 * kc + tig + 4], ah[3], al[3]);

            #pragma unroll
            for (int nt = 0; nt < 16; nt++) {
                const float* vp = SV + (8 * kc + tig) * SVS + 8 * nt + g;
                uint32_t bh0, bl0, bh1, bl1;
                tf_split(vp[0],       bh0, bl0);
                tf_split(vp[4 * SVS], bh1, bl1);
                mma_tf32(o[nt], ah, bh0, bh1);
                mma_tf32(o[nt], ah, bl0, bl1);
                mma_tf32(o[nt], al, bh0, bh1);
            }
        }
        __syncwarp();  // PV reads of SP done before next iter's stores
    }

    // ---- normalize + store ----
    float inv0 = 1.0f / l0;
    float inv1 = 1.0f / l1;
    const int r0 = qrow0 + wr + g;
    #pragma unroll
    for (int nt = 0; nt < 16; nt++) {
        int col = 8 * nt + 2 * tig;
        *(float2*)(out + (size_t)r0 * DIM + col) =
            make_float2(o[nt][0] * inv0, o[nt][1] * inv0);
        *(float2*)(out + (size_t)(r0 + 8) * DIM + col) =
            make_float2(o[nt][2] * inv1, o[nt][3] * inv1);
    }
}

extern "C" void kernel_launch(void* const* d_in, const int* in_sizes, int n_in,
                              void* d_out, int out_size) {
    const float* q = (const float*)d_in[0];
    const float* k = (const float*)d_in[1];
    const float* v = (const float*)d_in[2];
    float* out = (float*)d_out;

    const int smem_bytes = SMEM_FLOATS * (int)sizeof(float);  // 136,192 B
    cudaFuncSetAttribute(fa_tf32_kernel,
                         cudaFuncAttributeMaxDynamicSharedMemorySize, smem_bytes);

    dim3 grid(NSEQ / BM);   // 128 CTAs
    dim3 block(128);
    fa_tf32_kernel<<<grid, block, smem_bytes>>>(q, k, v, out);
}

// round 4
// speedup vs baseline: 2.1689x; 1.0012x over previous
#include <cuda_runtime.h>
#include <cstdint>

// FlashAttention via 3xTF32 mma.sync (emulated fp32 precision), sm_103a.
// N=8192, D=128, no softmax scaling.
// CTA: 128 threads (4 warps), BM=64 query rows (16/warp), BN=64 keys/iter.
// S = Ah*Bh + Ah*Bl + Al*Bh  (error ~eps^2, << 1e-3), same for P*V.

#define NSEQ 8192
#define DIM 128
#define BM 64
#define BN 64
#define SQK 132   // Q,K smem stride (floats): banks (4g+tig) conflict-free
#define SVS 136   // V smem stride: banks (8tig+g) conflict-free
#define SPS 132   // P smem stride

#define SMEM_FLOATS (BM * SQK + BN * SQK + BN * SVS + BM * SPS)

__device__ __forceinline__ uint32_t f2tf(float x) {
    uint32_t r;
    asm("cvt.rna.tf32.f32 %0, %1;" : "=r"(r) : "f"(x));
    return r;
}

// split x into tf32 hi + tf32 lo (x ~= hi + lo, residual ~eps^2*x)
__device__ __forceinline__ void tf_split(float x, uint32_t& hi, uint32_t& lo) {
    hi = f2tf(x);
    float l = x - __uint_as_float(hi);
    lo = f2tf(l);
}

__device__ __forceinline__ void mma_tf32(float* c, const uint32_t* a,
                                         uint32_t b0, uint32_t b1) {
    asm volatile(
        "mma.sync.aligned.m16n8k8.row.col.f32.tf32.tf32.f32 "
        "{%0,%1,%2,%3}, {%4,%5,%6,%7}, {%8,%9}, {%0,%1,%2,%3};"
        : "+f"(c[0]), "+f"(c[1]), "+f"(c[2]), "+f"(c[3])
        : "r"(a[0]), "r"(a[1]), "r"(a[2]), "r"(a[3]), "r"(b0), "r"(b1));
}

__global__ __launch_bounds__(128, 1)
void fa_tf32_kernel(const float* __restrict__ q,
                    const float* __restrict__ k,
                    const float* __restrict__ v,
                    float* __restrict__ out) {
    extern __shared__ float sm[];
    float* SQ = sm;                       // 64 x 132
    float* SK = SQ + BM * SQK;            // 64 x 132
    float* SV = SK + BN * SQK;            // 64 x 136
    float* SP = SV + BN * SVS;            // 64 x 132

    const int tid  = threadIdx.x;
    const int warp = tid >> 5;
    const int lane = tid & 31;
    const int g    = lane >> 2;   // group id (row within 8)
    const int tig  = lane & 3;    // thread in group
    const int wr   = warp * 16;   // this warp's row base in the 64-row tile
    const int qrow0 = blockIdx.x * BM;

    // ---- load Q tile once (fp32, stride 132) ----
    {
        const float4* qg = (const float4*)(q + (size_t)qrow0 * DIM);
        #pragma unroll
        for (int t = 0; t < 16; t++) {
            int i = tid + 128 * t;          // 2048 float4
            int row = i >> 5;
            int dd = (i & 31) << 2;
            *(float4*)(SQ + row * SQK + dd) = qg[i];
        }
    }

    // O accumulators: 16 n-tiles (D=128), c-frag layout
    float o[16][4];
    #pragma unroll
    for (int nt = 0; nt < 16; nt++)
        #pragma unroll
        for (int i = 0; i < 4; i++) o[nt][i] = 0.0f;

    float m0 = -1e30f, m1 = -1e30f, l0 = 0.0f, l1 = 0.0f;

    const float* Sq0 = SQ + (wr + g) * SQK;          // row g
    const float* Sq1 = Sq0 + 8 * SQK;                // row g+8
    float* Sp0w = SP + (wr + g) * SPS;
    float* Sp1w = Sp0w + 8 * SPS;

    #pragma unroll 1
    for (int kb = 0; kb < NSEQ / BN; kb++) {
        __syncthreads();  // previous iteration's SK/SV reads complete

        // ---- stream K,V tiles ----
        {
            const float4* kg = (const float4*)(k + (size_t)kb * BN * DIM);
            const float4* vg = (const float4*)(v + (size_t)kb * BN * DIM);
            #pragma unroll
            for (int t = 0; t < 16; t++) {
                int i = tid + 128 * t;
                int row = i >> 5;
                int dd = (i & 31) << 2;
                *(float4*)(SK + row * SQK + dd) = kg[i];
                *(float4*)(SV + row * SVS + dd) = vg[i];
            }
        }
        __syncthreads();

        // ---- S = Q K^T  (3x tf32 mma per tile) ----
        float s[8][4];
        #pragma unroll
        for (int nt = 0; nt < 8; nt++)
            #pragma unroll
            for (int i = 0; i < 4; i++) s[nt][i] = 0.0f;

        #pragma unroll 4
        for (int kc = 0; kc < DIM / 8; kc++) {
            uint32_t ah[4], al[4];
            tf_split(Sq0[8 * kc + tig],     ah[0], al[0]);
            tf_split(Sq1[8 * kc + tig],     ah[1], al[1]);
            tf_split(Sq0[8 * kc + tig + 4], ah[2], al[2]);
            tf_split(Sq1[8 * kc + tig + 4], ah[3], al[3]);

            #pragma unroll
            for (int nt = 0; nt < 8; nt++) {
                const float* kp = SK + (nt * 8 + g) * SQK + 8 * kc + tig;
                uint32_t bh0, bl0, bh1, bl1;
                tf_split(kp[0], bh0, bl0);
                tf_split(kp[4], bh1, bl1);
                mma_tf32(s[nt], ah, bh0, bh1);
                mma_tf32(s[nt], ah, bl0, bl1);
                mma_tf32(s[nt], al, bh0, bh1);
            }
        }

        // ---- online softmax (rows g and g+8; stats shared across quad) ----
        float mx0 = -1e30f, mx1 = -1e30f;
        #pragma unroll
        for (int nt = 0; nt < 8; nt++) {
            mx0 = fmaxf(mx0, fmaxf(s[nt][0], s[nt][1]));
            mx1 = fmaxf(mx1, fmaxf(s[nt][2], s[nt][3]));
        }
        mx0 = fmaxf(mx0, __shfl_xor_sync(0xffffffffu, mx0, 1));
        mx0 = fmaxf(mx0, __shfl_xor_sync(0xffffffffu, mx0, 2));
        mx1 = fmaxf(mx1, __shfl_xor_sync(0xffffffffu, mx1, 1));
        mx1 = fmaxf(mx1, __shfl_xor_sync(0xffffffffu, mx1, 2));

        float mn0 = fmaxf(m0, mx0);
        float mn1 = fmaxf(m1, mx1);
        float alpha0 = __expf(m0 - mn0);
        float alpha1 = __expf(m1 - mn1);
        m0 = mn0; m1 = mn1;

        float sum0 = 0.0f, sum1 = 0.0f;
        #pragma unroll
        for (int nt = 0; nt < 8; nt++) {
            s[nt][0] = __expf(s[nt][0] - mn0);
            s[nt][1] = __expf(s[nt][1] - mn0);
            s[nt][2] = __expf(s[nt][2] - mn1);
            s[nt][3] = __expf(s[nt][3] - mn1);
            sum0 += s[nt][0] + s[nt][1];
            sum1 += s[nt][2] + s[nt][3];
        }
        sum0 += __shfl_xor_sync(0xffffffffu, sum0, 1);
        sum0 += __shfl_xor_sync(0xffffffffu, sum0, 2);
        sum1 += __shfl_xor_sync(0xffffffffu, sum1, 1);
        sum1 += __shfl_xor_sync(0xffffffffu, sum1, 2);
        l0 = l0 * alpha0 + sum0;
        l1 = l1 * alpha1 + sum1;

        #pragma unroll
        for (int nt = 0; nt < 16; nt++) {
            o[nt][0] *= alpha0; o[nt][1] *= alpha0;
            o[nt][2] *= alpha1; o[nt][3] *= alpha1;
        }

        // ---- P to per-warp smem (read back as A-fragments) ----
        #pragma unroll
        for (int nt = 0; nt < 8; nt++) {
            *(float2*)(Sp0w + 8 * nt + 2 * tig) = make_float2(s[nt][0], s[nt][1]);
            *(float2*)(Sp1w + 8 * nt + 2 * tig) = make_float2(s[nt][2], s[nt][3]);
        }
        __syncwarp();

        // ---- O += P V  (3x tf32 mma per tile) ----
        #pragma unroll 2
        for (int kc = 0; kc < BN / 8; kc++) {
            uint32_t ah[4], al[4];
            tf_split(Sp0w[8 * kc + tig],     ah[0], al[0]);
            tf_split(Sp1w[8 * kc + tig],     ah[1], al[1]);
            tf_split(Sp0w[8 * kc + tig + 4], ah[2], al[2]);
            tf_split(Sp1w[8 * kc + tig + 4], ah[3], al[3]);

            #pragma unroll
            for (int nt = 0; nt < 16; nt++) {
                const float* vp = SV + (8 * kc + tig) * SVS + 8 * nt + g;
                uint32_t bh0, bl0, bh1, bl1;
                tf_split(vp[0],       bh0, bl0);
                tf_split(vp[4 * SVS], bh1, bl1);
                mma_tf32(o[nt], ah, bh0, bh1);
                mma_tf32(o[nt], ah, bl0, bl1);
                mma_tf32(o[nt], al, bh0, bh1);
            }
        }
        __syncwarp();  // PV reads of SP done before next iter's stores
    }

    // ---- normalize + store ----
    float inv0 = 1.0f / l0;
    float inv1 = 1.0f / l1;
    const int r0 = qrow0 + wr + g;
    #pragma unroll
    for (int nt = 0; nt < 16; nt++) {
        int col = 8 * nt + 2 * tig;
        *(float2*)(out + (size_t)r0 * DIM + col) =
            make_float2(o[nt][0] * inv0, o[nt][1] * inv0);
        *(float2*)(out + (size_t)(r0 + 8) * DIM + col) =
            make_float2(o[nt][2] * inv1, o[nt][3] * inv1);
    }
}

extern "C" void kernel_launch(void* const* d_in, const int* in_sizes, int n_in,
                              void* d_out, int out_size) {
    const float* q = (const float*)d_in[0];
    const float* k = (const float*)d_in[1];
    const float* v = (const float*)d_in[2];
    float* out = (float*)d_out;

    const int smem_bytes = SMEM_FLOATS * (int)sizeof(float);  // 136,192 B
    cudaFuncSetAttribute(fa_tf32_kernel,
                         cudaFuncAttributeMaxDynamicSharedMemorySize, smem_bytes);

    dim3 grid(NSEQ / BM);   // 128 CTAs
    dim3 block(128);
    fa_tf32_kernel<<<grid, block, smem_bytes>>>(q, k, v, out);
}

// round 5
// speedup vs baseline: 2.5921x; 1.1951x over previous
#include <cuda_runtime.h>
#include <cstdint>

// FlashAttention via 3xTF32 mma.sync, 8-warp N-split, pre-split K/V in smem.
// N=8192, D=128, no softmax scaling. sm_103a.
// CTA: 256 threads (8 warps), BM=64 rows, BN=64 keys/iter.
// warp = (rg = warp&3 -> rows rg*16..+15, h = warp>>2 -> key half h*32..+31).
// K,V stored as tf32 hi/lo pairs (split once at load). Q,P split in regs.

#define NSEQ 8192
#define DIM 128
#define BM 64
#define BN 64
#define SQK 132   // Q,K stride (floats): (4g+tig) banks conflict-free
#define SVS 136   // V stride: (8tig+g) banks conflict-free
#define SPS 132

#define SMEM_FLOATS (BM*SQK + 2*(BN*SQK) + 2*(BN*SVS) + BM*SPS + 256)

__device__ __forceinline__ uint32_t f2tf(float x) {
    uint32_t r;
    asm("cvt.rna.tf32.f32 %0, %1;" : "=r"(r) : "f"(x));
    return r;
}
__device__ __forceinline__ void tf_split(float x, uint32_t& hi, uint32_t& lo) {
    hi = f2tf(x);
    lo = f2tf(x - __uint_as_float(hi));
}
__device__ __forceinline__ void split1(float x, float& h, float& l) {
    uint32_t uh = f2tf(x);
    h = __uint_as_float(uh);
    l = __uint_as_float(f2tf(x - h));
}
__device__ __forceinline__ void mma_tf32(float* c, const uint32_t* a,
                                         uint32_t b0, uint32_t b1) {
    asm volatile(
        "mma.sync.aligned.m16n8k8.row.col.f32.tf32.tf32.f32 "
        "{%0,%1,%2,%3}, {%4,%5,%6,%7}, {%8,%9}, {%0,%1,%2,%3};"
        : "+f"(c[0]), "+f"(c[1]), "+f"(c[2]), "+f"(c[3])
        : "r"(a[0]), "r"(a[1]), "r"(a[2]), "r"(a[3]), "r"(b0), "r"(b1));
}

__global__ __launch_bounds__(256, 1)
void fa_tf32_kernel(const float* __restrict__ q,
                    const float* __restrict__ k,
                    const float* __restrict__ v,
                    float* __restrict__ out) {
    extern __shared__ float sm[];
    float* SQ  = sm;                      // 64 x 132 fp32
    float* SKh = SQ  + BM * SQK;          // 64 x 132 tf32-hi
    float* SKl = SKh + BN * SQK;          // 64 x 132 tf32-lo
    float* SVh = SKl + BN * SQK;          // 64 x 136
    float* SVl = SVh + BN * SVS;          // 64 x 136
    float* SP  = SVl + BN * SVS;          // 64 x 132 fp32
    float* SMx = SP  + BM * SPS;          // 2 x 64
    float* SSm = SMx + 128;               // 2 x 64

    const int tid  = threadIdx.x;
    const int warp = tid >> 5;
    const int lane = tid & 31;
    const int g    = lane >> 2;
    const int tig  = lane & 3;
    const int rg   = warp & 3;     // row group
    const int h    = warp >> 2;    // key half
    const int wr   = rg * 16;
    const int qrow0 = blockIdx.x * BM;

    // ---- load Q tile (fp32) ----
    {
        const float4* qg = (const float4*)(q + (size_t)qrow0 * DIM);
        #pragma unroll
        for (int t = 0; t < 8; t++) {
            int i = tid + 256 * t;       // 2048 float4
            int row = i >> 5;
            int dd = (i & 31) << 2;
            *(float4*)(SQ + row * SQK + dd) = qg[i];
        }
    }

    float o[16][4];
    #pragma unroll
    for (int nt = 0; nt < 16; nt++)
        #pragma unroll
        for (int i = 0; i < 4; i++) o[nt][i] = 0.0f;
    float m0 = -1e30f, m1 = -1e30f, l0 = 0.0f, l1 = 0.0f;

    const float* Sq0 = SQ + (wr + g) * SQK;
    const float* Sq1 = Sq0 + 8 * SQK;
    float* Sp0 = SP + (wr + g) * SPS;
    float* Sp1 = Sp0 + 8 * SPS;

    #pragma unroll 1
    for (int kb = 0; kb < NSEQ / BN; kb++) {
        __syncthreads();   // prior iter's smem reads complete

        // ---- stream K,V; split to hi/lo once ----
        {
            const float4* kg = (const float4*)(k + (size_t)kb * BN * DIM);
            const float4* vg = (const float4*)(v + (size_t)kb * BN * DIM);
            #pragma unroll
            for (int t = 0; t < 8; t++) {
                int i = tid + 256 * t;
                int row = i >> 5;
                int dd = (i & 31) << 2;
                float4 kx = kg[i], vx = vg[i];
                float4 khv, klv, vhv, vlv;
                split1(kx.x, khv.x, klv.x); split1(kx.y, khv.y, klv.y);
                split1(kx.z, khv.z, klv.z); split1(kx.w, khv.w, klv.w);
                split1(vx.x, vhv.x, vlv.x); split1(vx.y, vhv.y, vlv.y);
                split1(vx.z, vhv.z, vlv.z); split1(vx.w, vhv.w, vlv.w);
                *(float4*)(SKh + row * SQK + dd) = khv;
                *(float4*)(SKl + row * SQK + dd) = klv;
                *(float4*)(SVh + row * SVS + dd) = vhv;
                *(float4*)(SVl + row * SVS + dd) = vlv;
            }
        }
        __syncthreads();

        // ---- S = Q K^T over this warp's key half (4 n-tiles) ----
        float s[4][4];
        #pragma unroll
        for (int nt = 0; nt < 4; nt++)
            #pragma unroll
            for (int i = 0; i < 4; i++) s[nt][i] = 0.0f;

        #pragma unroll 4
        for (int kc = 0; kc < DIM / 8; kc++) {
            uint32_t ah[4], al[4];
            tf_split(Sq0[8 * kc + tig],     ah[0], al[0]);
            tf_split(Sq1[8 * kc + tig],     ah[1], al[1]);
            tf_split(Sq0[8 * kc + tig + 4], ah[2], al[2]);
            tf_split(Sq1[8 * kc + tig + 4], ah[3], al[3]);
            #pragma unroll
            for (int nt = 0; nt < 4; nt++) {
                int ntg = h * 4 + nt;
                const float* kph = SKh + (ntg * 8 + g) * SQK + 8 * kc + tig;
                const float* kpl = SKl + (ntg * 8 + g) * SQK + 8 * kc + tig;
                uint32_t bh0 = __float_as_uint(kph[0]);
                uint32_t bh1 = __float_as_uint(kph[4]);
                uint32_t bl0 = __float_as_uint(kpl[0]);
                uint32_t bl1 = __float_as_uint(kpl[4]);
                mma_tf32(s[nt], ah, bh0, bh1);
                mma_tf32(s[nt], ah, bl0, bl1);
                mma_tf32(s[nt], al, bh0, bh1);
            }
        }

        // ---- softmax: cross-half stat exchange ----
        float mx0 = -1e30f, mx1 = -1e30f;
        #pragma unroll
        for (int nt = 0; nt < 4; nt++) {
            mx0 = fmaxf(mx0, fmaxf(s[nt][0], s[nt][1]));
            mx1 = fmaxf(mx1, fmaxf(s[nt][2], s[nt][3]));
        }
        mx0 = fmaxf(mx0, __shfl_xor_sync(0xffffffffu, mx0, 1));
        mx0 = fmaxf(mx0, __shfl_xor_sync(0xffffffffu, mx0, 2));
        mx1 = fmaxf(mx1, __shfl_xor_sync(0xffffffffu, mx1, 1));
        mx1 = fmaxf(mx1, __shfl_xor_sync(0xffffffffu, mx1, 2));
        if (tig == 0) {
            SMx[h * 64 + wr + g]     = mx0;
            SMx[h * 64 + wr + 8 + g] = mx1;
        }
        __syncthreads();
        mx0 = fmaxf(mx0, SMx[(1 - h) * 64 + wr + g]);
        mx1 = fmaxf(mx1, SMx[(1 - h) * 64 + wr + 8 + g]);

        float mn0 = fmaxf(m0, mx0), mn1 = fmaxf(m1, mx1);
        float alpha0 = __expf(m0 - mn0), alpha1 = __expf(m1 - mn1);
        m0 = mn0; m1 = mn1;

        float sum0 = 0.0f, sum1 = 0.0f;
        #pragma unroll
        for (int nt = 0; nt < 4; nt++) {
            s[nt][0] = __expf(s[nt][0] - mn0);
            s[nt][1] = __expf(s[nt][1] - mn0);
            s[nt][2] = __expf(s[nt][2] - mn1);
            s[nt][3] = __expf(s[nt][3] - mn1);
            sum0 += s[nt][0] + s[nt][1];
            sum1 += s[nt][2] + s[nt][3];
        }
        sum0 += __shfl_xor_sync(0xffffffffu, sum0, 1);
        sum0 += __shfl_xor_sync(0xffffffffu, sum0, 2);
        sum1 += __shfl_xor_sync(0xffffffffu, sum1, 1);
        sum1 += __shfl_xor_sync(0xffffffffu, sum1, 2);
        if (tig == 0) {
            SSm[h * 64 + wr + g]     = sum0;
            SSm[h * 64 + wr + 8 + g] = sum1;
        }
        // write P (own rows, own key-half columns)
        #pragma unroll
        for (int nt = 0; nt < 4; nt++) {
            int ntg = h * 4 + nt;
            *(float2*)(Sp0 + ntg * 8 + 2 * tig) = make_float2(s[nt][0], s[nt][1]);
            *(float2*)(Sp1 + ntg * 8 + 2 * tig) = make_float2(s[nt][2], s[nt][3]);
        }
        __syncthreads();
        sum0 += SSm[(1 - h) * 64 + wr + g];
        sum1 += SSm[(1 - h) * 64 + wr + 8 + g];
        l0 = l0 * alpha0 + sum0;
        l1 = l1 * alpha1 + sum1;

        #pragma unroll
        for (int nt = 0; nt < 16; nt++) {
            o[nt][0] *= alpha0; o[nt][1] *= alpha0;
            o[nt][2] *= alpha1; o[nt][3] *= alpha1;
        }

        // ---- O += P V over this warp's j-half ----
        #pragma unroll 2
        for (int kcl = 0; kcl < 4; kcl++) {
            int kcg = h * 4 + kcl;
            uint32_t ah[4], al[4];
            tf_split(Sp0[8 * kcg + tig],     ah[0], al[0]);
            tf_split(Sp1[8 * kcg + tig],     ah[1], al[1]);
            tf_split(Sp0[8 * kcg + tig + 4], ah[2], al[2]);
            tf_split(Sp1[8 * kcg + tig + 4], ah[3], al[3]);
            #pragma unroll
            for (int nt = 0; nt < 16; nt++) {
                const float* vph = SVh + (8 * kcg + tig) * SVS + 8 * nt + g;
                const float* vpl = SVl + (8 * kcg + tig) * SVS + 8 * nt + g;
                uint32_t bh0 = __float_as_uint(vph[0]);
                uint32_t bh1 = __float_as_uint(vph[4 * SVS]);
                uint32_t bl0 = __float_as_uint(vpl[0]);
                uint32_t bl1 = __float_as_uint(vpl[4 * SVS]);
                mma_tf32(o[nt], ah, bh0, bh1);
                mma_tf32(o[nt], ah, bl0, bl1);
                mma_tf32(o[nt], al, bh0, bh1);
            }
        }
    }

    // ---- epilogue: combine halves via smem (reuse SKh), normalize, store ----
    __syncthreads();
    float* OB = SKh;   // 64 x 132
    if (h == 0) {
        #pragma unroll
        for (int nt = 0; nt < 16; nt++) {
            *(float2*)(OB + (wr + g) * SQK + 8 * nt + 2 * tig) =
                make_float2(o[nt][0], o[nt][1]);
            *(float2*)(OB + (wr + 8 + g) * SQK + 8 * nt + 2 * tig) =
                make_float2(o[nt][2], o[nt][3]);
        }
    }
    __syncthreads();
    if (h == 1) {
        float inv0 = 1.0f / l0, inv1 = 1.0f / l1;
        const int r0 = qrow0 + wr + g;
        #pragma unroll
        for (int nt = 0; nt < 16; nt++) {
            int col = 8 * nt + 2 * tig;
            float2 p0 = *(float2*)(OB + (wr + g) * SQK + col);
            float2 p1 = *(float2*)(OB + (wr + 8 + g) * SQK + col);
            *(float2*)(out + (size_t)r0 * DIM + col) =
                make_float2((p0.x + o[nt][0]) * inv0, (p0.y + o[nt][1]) * inv0);
            *(float2*)(out + (size_t)(r0 + 8) * DIM + col) =
                make_float2((p1.x + o[nt][2]) * inv1, (p1.y + o[nt][3]) * inv1);
        }
    }
}

extern "C" void kernel_launch(void* const* d_in, const int* in_sizes, int n_in,
                              void* d_out, int out_size) {
    const float* q = (const float*)d_in[0];
    const float* k = (const float*)d_in[1];
    const float* v = (const float*)d_in[2];
    float* out = (float*)d_out;

    const int smem_bytes = SMEM_FLOATS * (int)sizeof(float);  // 205,824 B
    cudaFuncSetAttribute(fa_tf32_kernel,
                         cudaFuncAttributeMaxDynamicSharedMemorySize, smem_bytes);

    dim3 grid(NSEQ / BM);   // 128 CTAs
    dim3 block(256);
    fa_tf32_kernel<<<grid, block, smem_bytes>>>(q, k, v, out);
}